// round 9
// baseline (speedup 1.0000x reference)
#include <cuda_runtime.h>
#include <math.h>

// SE(3) exp + point transform, single kernel, NO block barrier.
// out[bt,n,:] = R(dofs[bt]) * X[bt,n,:] + t(dofs[bt])
// X_v: [B,T,N,3] f32, dofs: [B,T,6] f32, out: [B,T,N,3] f32. B=64,T=28,N=4096.
//
// Proven-fastest body (R6): lane 0 of each warp computes R,t, broadcast via
// __shfl_sync; each thread does 3x float4 load -> 36 FMA -> 3x float4 store
// (MLP_p1=3, the empirical sweet spot). This round: 512-thread blocks to
// halve the grid (3584 blocks) and cut launch overhead; no barrier means
// block size does not couple warps.

#define THREADS 512

__global__ void __launch_bounds__(THREADS)
se3_transform_kernel(const float* __restrict__ X,
                     const float* __restrict__ dofs,
                     float* __restrict__ out)
{
    // Flat tile index (1 tile = 4 points = 12 floats). 1024 tiles per bt
    // slice; a warp spans 32 consecutive tiles -> all lanes of a warp share
    // the same bt (1024 % 32 == 0).
    const unsigned tile = blockIdx.x * THREADS + threadIdx.x;
    const unsigned bt   = tile >> 10;
    const int lane      = threadIdx.x & 31;

    const size_t base = (size_t)tile * 12;       // float offset
    const float4* __restrict__ src = reinterpret_cast<const float4*>(X + base);
    float4* __restrict__ dst = reinterpret_cast<float4*>(out + base);

    // ---- issue data loads FIRST (independent of R,t) ----
    const float4 a = __ldcs(&src[0]);   // x0 y0 z0 x1
    const float4 b = __ldcs(&src[1]);   // y1 z1 x2 y2
    const float4 c = __ldcs(&src[2]);   // z2 x3 y3 z3

    // ---- lane 0 computes R,t (hidden under load latency) ----
    float r00, r01, r02, r10, r11, r12, r20, r21, r22, t0, t1, t2;
    if (lane == 0) {
        const float* d = dofs + bt * 6;
        const float tx = __ldg(&d[0]), ty = __ldg(&d[1]), tz = __ldg(&d[2]);
        const float wx = __ldg(&d[3]), wy = __ldg(&d[4]), wz = __ldg(&d[5]);

        const float nrm   = wx*wx + wy*wy + wz*wz;
        const float th2c  = fmaxf(nrm, 1.0e-4f);   // clip BEFORE sqrt (matches ref)
        const float theta = sqrtf(th2c);
        float st, ct;
        sincosf(theta, &st, &ct);
        const float inv_t  = 1.0f / theta;
        const float inv_t2 = inv_t * inv_t;
        const float f1 = st * inv_t;
        const float f2 = (1.0f - ct) * inv_t2;
        const float f3 = (theta - st) * inv_t2 * inv_t;

        // H2 = H@H = w w^T - (w.w) I  (raw nrm, matches ref)
        const float h2xx = wx*wx - nrm, h2yy = wy*wy - nrm, h2zz = wz*wz - nrm;
        const float h2xy = wx*wy, h2xz = wx*wz, h2yz = wy*wz;

        r00 = 1.0f + f2*h2xx;
        r01 = -f1*wz + f2*h2xy;
        r02 =  f1*wy + f2*h2xz;
        r10 =  f1*wz + f2*h2xy;
        r11 = 1.0f + f2*h2yy;
        r12 = -f1*wx + f2*h2yz;
        r20 = -f1*wy + f2*h2xz;
        r21 =  f1*wx + f2*h2yz;
        r22 = 1.0f + f2*h2zz;

        const float v00 = 1.0f + f3*h2xx;
        const float v01 = -f2*wz + f3*h2xy;
        const float v02 =  f2*wy + f3*h2xz;
        const float v10 =  f2*wz + f3*h2xy;
        const float v11 = 1.0f + f3*h2yy;
        const float v12 = -f2*wx + f3*h2yz;
        const float v20 = -f2*wy + f3*h2xz;
        const float v21 =  f2*wx + f3*h2yz;
        const float v22 = 1.0f + f3*h2zz;

        t0 = v00*tx + v01*ty + v02*tz;
        t1 = v10*tx + v11*ty + v12*tz;
        t2 = v20*tx + v21*ty + v22*tz;
    }

    // ---- warp broadcast (no smem, no block barrier) ----
    r00 = __shfl_sync(0xffffffffu, r00, 0);
    r01 = __shfl_sync(0xffffffffu, r01, 0);
    r02 = __shfl_sync(0xffffffffu, r02, 0);
    r10 = __shfl_sync(0xffffffffu, r10, 0);
    r11 = __shfl_sync(0xffffffffu, r11, 0);
    r12 = __shfl_sync(0xffffffffu, r12, 0);
    r20 = __shfl_sync(0xffffffffu, r20, 0);
    r21 = __shfl_sync(0xffffffffu, r21, 0);
    r22 = __shfl_sync(0xffffffffu, r22, 0);
    t0  = __shfl_sync(0xffffffffu, t0, 0);
    t1  = __shfl_sync(0xffffffffu, t1, 0);
    t2  = __shfl_sync(0xffffffffu, t2, 0);

    // ---- transform 4 points ----
    const float o0x = fmaf(r00, a.x, fmaf(r01, a.y, fmaf(r02, a.z, t0)));
    const float o0y = fmaf(r10, a.x, fmaf(r11, a.y, fmaf(r12, a.z, t1)));
    const float o0z = fmaf(r20, a.x, fmaf(r21, a.y, fmaf(r22, a.z, t2)));

    const float o1x = fmaf(r00, a.w, fmaf(r01, b.x, fmaf(r02, b.y, t0)));
    const float o1y = fmaf(r10, a.w, fmaf(r11, b.x, fmaf(r12, b.y, t1)));
    const float o1z = fmaf(r20, a.w, fmaf(r21, b.x, fmaf(r22, b.y, t2)));

    const float o2x = fmaf(r00, b.z, fmaf(r01, b.w, fmaf(r02, c.x, t0)));
    const float o2y = fmaf(r10, b.z, fmaf(r11, b.w, fmaf(r12, c.x, t1)));
    const float o2z = fmaf(r20, b.z, fmaf(r21, b.w, fmaf(r22, c.x, t2)));

    const float o3x = fmaf(r00, c.y, fmaf(r01, c.z, fmaf(r02, c.w, t0)));
    const float o3y = fmaf(r10, c.y, fmaf(r11, c.z, fmaf(r12, c.w, t1)));
    const float o3z = fmaf(r20, c.y, fmaf(r21, c.z, fmaf(r22, c.w, t2)));

    __stcs(&dst[0], make_float4(o0x, o0y, o0z, o1x));
    __stcs(&dst[1], make_float4(o1y, o1z, o2x, o2y));
    __stcs(&dst[2], make_float4(o2z, o3x, o3y, o3z));
}

extern "C" void kernel_launch(void* const* d_in, const int* in_sizes, int n_in,
                              void* d_out, int out_size)
{
    const float* X    = (const float*)d_in[0];   // [B,T,N,3]
    const float* dofs = (const float*)d_in[1];   // [B,T,6]

    const int nBT = in_sizes[1] / 6;             // 1792
    const int N   = (in_sizes[0] / nBT) / 3;     // 4096

    const int totalTiles = nBT * (N * 3 / 12);   // 1792 * 1024
    const int blocks = totalTiles / THREADS;     // 3584

    se3_transform_kernel<<<blocks, THREADS>>>(X, dofs, (float*)d_out);
}